// round 6
// baseline (speedup 1.0000x reference)
#include <cuda_runtime.h>

#define EMB   100
#define BOT   5
#define B_    128
#define S_    2048
#define V_    50257
#define R_    4                     // gather CTAs per row
#define TOKC  (S_ / R_)             // 512 tokens per gather CTA
#define HISTW ((V_ + 1) / 2)
#define HISTPAD ((HISTW + 3) & ~3)
#define FULLMASK 0xffffffffu

// Static device scratch (no allocation allowed)
__device__ float g_w[B_ * S_];            // per-token tfidf weight
__device__ float g_part[B_ * R_ * EMB];   // per-gather-CTA doc partials
__device__ int   g_cnt[B_];               // completion counters (reset by K1)

// ---------------------------------------------------------------------------
// K1: per-row histogram + Z + per-token weights. One CTA per row.
// ---------------------------------------------------------------------------
__global__ void __launch_bounds__(1024, 1)
k1_weights(const int* __restrict__ x, const float* __restrict__ idf)
{
    extern __shared__ unsigned int hist[];   // HISTPAD words (packed 16-bit)
    __shared__ float zp[32];

    const int b    = blockIdx.x;
    const int tid  = threadIdx.x;
    const int warp = tid >> 5;
    const int lane = tid & 31;

    // token pair load first (coalesced LDG.64); latency hides behind zeroing
    const int* xr = x + b * S_;
    const int2 tt = *(const int2*)(xr + (warp << 6) + (lane << 1));

    // zero histogram (vectorized)
    uint4* h4 = (uint4*)hist;
    const uint4 z4 = make_uint4(0u, 0u, 0u, 0u);
    for (int i = tid; i < (HISTPAD >> 2); i += 1024) h4[i] = z4;

    // independent gathers issue before the barrier
    const float idf0 = __ldg(&idf[tt.x]);
    const float idf1 = __ldg(&idf[tt.y]);
    if (tid == 0) g_cnt[b] = 0;              // reset tail counter for K2
    __syncthreads();

    // histogram + Z
    atomicAdd(&hist[tt.x >> 1], 1u << ((tt.x & 1) << 4));
    atomicAdd(&hist[tt.y >> 1], 1u << ((tt.y & 1) << 4));

    float z = idf0 + idf1;
    #pragma unroll
    for (int o = 16; o; o >>= 1) z += __shfl_xor_sync(FULLMASK, z, o);
    if (lane == 0) zp[warp] = z;
    __syncthreads();                          // also orders histogram atomics

    float zz = 0.f;
    #pragma unroll
    for (int i = 0; i < 32; i++) zz += zp[i];
    const float invZ = 1.0f / zz;

    const float c0 = (float)((hist[tt.x >> 1] >> ((tt.x & 1) << 4)) & 0xFFFFu)
                     * idf0 * invZ;
    const float c1 = (float)((hist[tt.y >> 1] >> ((tt.y & 1) << 4)) & 0xFFFFu)
                     * idf1 * invZ;
    *(float2*)(g_w + b * S_ + (warp << 6) + (lane << 1)) = make_float2(c0, c1);
}

// ---------------------------------------------------------------------------
// K2: weighted embedding gather. 4 CTAs per row, 256 threads each.
// Last CTA of each row reduces the 4 partials and runs the tiny MLP.
// ---------------------------------------------------------------------------
__global__ void __launch_bounds__(256)
k2_gather(const int* __restrict__ x, const float* __restrict__ we,
          const float* __restrict__ fc1w, const float* __restrict__ fc1b,
          const float* __restrict__ fc2w, const float* __restrict__ fc2b,
          float* __restrict__ out)
{
    __shared__ float stage[8 * 128];   // per-warp (offset,coef) pairs
    __shared__ float part[8 * EMB];    // per-warp partials
    __shared__ float doc[EMB];
    __shared__ float hv[8];
    __shared__ int   isLast;

    const int tid  = threadIdx.x;
    const int warp = tid >> 5;
    const int lane = tid & 31;
    const int b    = blockIdx.x >> 2;
    const int r    = blockIdx.x & (R_ - 1);

    // coalesced loads of this warp's 64 (token, weight) pairs
    const int s0 = r * TOKC + (warp << 6);
    const int2   tt = *(const int2*)  (x   + b * S_ + s0 + (lane << 1));
    const float2 cc = *(const float2*)(g_w + b * S_ + s0 + (lane << 1));

    float4* stW = (float4*)(stage + (warp << 7));
    stW[lane] = make_float4(__int_as_float(tt.x * (EMB * 4)), cc.x,
                            __int_as_float(tt.y * (EMB * 4)), cc.y);
    __syncwarp();

    const bool active = lane < (EMB / 4);
    const int  eoff   = lane << 4;
    const char* web = (const char*)we;
    float4 a0 = make_float4(0.f, 0.f, 0.f, 0.f);
    float4 a1 = make_float4(0.f, 0.f, 0.f, 0.f);

    #pragma unroll 8
    for (int k = 0; k < 32; k++) {
        const float4 q = stW[k];             // broadcast: o1,c1,o2,c2
        if (active) {
            const float4 e1 = *(const float4*)(web + __float_as_int(q.x) + eoff);
            const float4 e2 = *(const float4*)(web + __float_as_int(q.z) + eoff);
            a0.x += q.y * e1.x; a0.y += q.y * e1.y;
            a0.z += q.y * e1.z; a0.w += q.y * e1.w;
            a1.x += q.w * e2.x; a1.y += q.w * e2.y;
            a1.z += q.w * e2.z; a1.w += q.w * e2.w;
        }
    }
    if (active) {
        a0.x += a1.x; a0.y += a1.y; a0.z += a1.z; a0.w += a1.w;
        ((float4*)(part + warp * EMB))[lane] = a0;
    }
    __syncthreads();

    // CTA partial -> global (deterministic order)
    if (tid < EMB) {
        float d = 0.f;
        #pragma unroll
        for (int w = 0; w < 8; w++) d += part[w * EMB + tid];
        g_part[blockIdx.x * EMB + tid] = d;
    }
    __threadfence();
    __syncthreads();
    if (tid == 0) isLast = (atomicAdd(&g_cnt[b], 1) == R_ - 1);
    __syncthreads();
    if (!isLast) return;

    // last CTA of row b: reduce partials (fixed order) + MLP
    __threadfence();
    if (tid < EMB) {
        const float* base = g_part + b * R_ * EMB;
        float d = 0.f;
        #pragma unroll
        for (int rr = 0; rr < R_; rr++) d += __ldcg(base + rr * EMB + tid);
        doc[tid] = d;
    }
    __syncthreads();
    if (tid < BOT) {
        float h = __ldg(&fc1b[tid]);
        #pragma unroll
        for (int e = 0; e < EMB; e++) h += doc[e] * __ldg(&fc1w[tid * EMB + e]);
        hv[tid] = h;
    }
    __syncthreads();
    if (tid < EMB) {
        float o = __ldg(&fc2b[tid]);
        #pragma unroll
        for (int j = 0; j < BOT; j++) o += hv[j] * __ldg(&fc2w[tid * BOT + j]);
        out[b * EMB + tid] = o;
    }
}

extern "C" void kernel_launch(void* const* d_in, const int* in_sizes, int n_in,
                              void* d_out, int out_size)
{
    const int*   x    = (const int*)  d_in[0];   // [B,S] int32 token ids
    const float* we   = (const float*)d_in[1];   // [V,EMB]
    const float* idf  = (const float*)d_in[2];   // [V]
    const float* fc1w = (const float*)d_in[3];   // [BOT,EMB]
    const float* fc1b = (const float*)d_in[4];   // [BOT]
    const float* fc2w = (const float*)d_in[5];   // [EMB,BOT]
    const float* fc2b = (const float*)d_in[6];   // [EMB]
    float* out = (float*)d_out;                  // [B,EMB]

    size_t smem1 = (size_t)HISTPAD * 4;
    cudaFuncSetAttribute(k1_weights,
                         cudaFuncAttributeMaxDynamicSharedMemorySize,
                         (int)smem1);

    k1_weights<<<B_, 1024, smem1>>>(x, idf);
    k2_gather<<<B_ * R_, 256>>>(x, we, fc1w, fc1b, fc2w, fc2b, out);
}

// round 7
// speedup vs baseline: 1.3750x; 1.3750x over previous
#include <cuda_runtime.h>

#define EMB 100
#define BOT 5
#define NT  512                      // 16 warps -> 128-reg budget per thread
#define FULLMASK 0xffffffffu

// One CTA per document row, 512 threads.
// Smem layout (dynamic, 16B-aligned sections):
//   uint32 hist[histPad]    packed 16-bit token counts (counts <= 2048 < 65536)
//   float  stage[16*256]    per-warp (offset,coef) pairs: 128 pairs/warp
//   float  partial[16*EMB]  per-warp doc partials (deterministic reduction)
//   float  zp[16], doc[EMB], hv[8]
__global__ void __launch_bounds__(NT, 1)
doc_model_kernel(const int* __restrict__ x,
                 const float* __restrict__ we,
                 const float* __restrict__ idf,
                 const float* __restrict__ fc1w,
                 const float* __restrict__ fc1b,
                 const float* __restrict__ fc2w,
                 const float* __restrict__ fc2b,
                 float* __restrict__ out,
                 int S, int V)
{
    extern __shared__ unsigned int smem[];
    const int histPad = ((((V + 1) >> 1) + 3) & ~3);
    unsigned int* hist = smem;                    // histPad words
    float* stage   = (float*)(hist + histPad);    // 16 warps * 256 floats
    float* partial = stage + 16 * 256;            // 16*EMB
    float* zp      = partial + 16 * EMB;          // 16
    float* doc     = zp + 16;                     // EMB
    float* hv      = doc + EMB;                   // 8

    const int tid  = threadIdx.x;
    const int warp = tid >> 5;
    const int lane = tid & 31;

    // ---- token load first (one LDG.128): warp w owns tokens [128w, 128w+128),
    // lane l holds tokens 128w + 4l + {0,1,2,3}. Latency hides behind zeroing.
    const int* xr = x + (long long)blockIdx.x * S;
    const int4 t4 = *(const int4*)(xr + (warp << 7) + (lane << 2));

    // ---- zero histogram (vectorized) ----
    uint4* h4 = (uint4*)hist;
    const uint4 z4 = make_uint4(0u, 0u, 0u, 0u);
    for (int i = tid; i < (histPad >> 2); i += NT) h4[i] = z4;

    // idf gathers are independent of the histogram: issue before the barrier
    const float i0 = __ldg(&idf[t4.x]);
    const float i1 = __ldg(&idf[t4.y]);
    const float i2 = __ldg(&idf[t4.z]);
    const float i3 = __ldg(&idf[t4.w]);
    __syncthreads();

    // ---- phase 1: histogram + Z ----
    atomicAdd(&hist[t4.x >> 1], 1u << ((t4.x & 1) << 4));
    atomicAdd(&hist[t4.y >> 1], 1u << ((t4.y & 1) << 4));
    atomicAdd(&hist[t4.z >> 1], 1u << ((t4.z & 1) << 4));
    atomicAdd(&hist[t4.w >> 1], 1u << ((t4.w & 1) << 4));

    float z = (i0 + i1) + (i2 + i3);
    #pragma unroll
    for (int o = 16; o; o >>= 1) z += __shfl_xor_sync(FULLMASK, z, o);
    if (lane == 0) zp[warp] = z;
    __syncthreads();                               // also orders the atomics

    float zz = 0.f;
    #pragma unroll
    for (int i = 0; i < 16; i++) zz += zp[i];
    const float invZ = 1.0f / zz;

    // ---- coefficients + staging: lane l writes slots 2l and 2l+1 of the
    // warp strip; slot j packs pair (o,c) for tokens 2j and 2j+1.
    const float c0 = (float)((hist[t4.x >> 1] >> ((t4.x & 1) << 4)) & 0xFFFFu) * i0 * invZ;
    const float c1 = (float)((hist[t4.y >> 1] >> ((t4.y & 1) << 4)) & 0xFFFFu) * i1 * invZ;
    const float c2 = (float)((hist[t4.z >> 1] >> ((t4.z & 1) << 4)) & 0xFFFFu) * i2 * invZ;
    const float c3 = (float)((hist[t4.w >> 1] >> ((t4.w & 1) << 4)) & 0xFFFFu) * i3 * invZ;
    float4* stW = (float4*)(stage + (warp << 8));
    stW[(lane << 1)]     = make_float4(__int_as_float(t4.x * (EMB * 4)), c0,
                                       __int_as_float(t4.y * (EMB * 4)), c1);
    stW[(lane << 1) + 1] = make_float4(__int_as_float(t4.z * (EMB * 4)), c2,
                                       __int_as_float(t4.w * (EMB * 4)), c3);
    __syncwarp();

    // ---- phase 2: doc += coef * emb[t]. Explicit MLP pipeline: per chunk,
    // 4 broadcast LDS.128 then 8 independent LDG.128, then the FMAs.
    const bool active = lane < (EMB / 4);   // 25 lanes carry the embedding row
    const int  eoff   = lane << 4;
    const char* web = (const char*)we;
    float4 acc0 = make_float4(0.f, 0.f, 0.f, 0.f);
    float4 acc1 = make_float4(0.f, 0.f, 0.f, 0.f);

    #pragma unroll 2
    for (int kk = 0; kk < 64; kk += 4) {
        const float4 q0 = stW[kk];
        const float4 q1 = stW[kk + 1];
        const float4 q2 = stW[kk + 2];
        const float4 q3 = stW[kk + 3];
        if (active) {
            const float4 ea = *(const float4*)(web + __float_as_int(q0.x) + eoff);
            const float4 eb = *(const float4*)(web + __float_as_int(q0.z) + eoff);
            const float4 ec = *(const float4*)(web + __float_as_int(q1.x) + eoff);
            const float4 ed = *(const float4*)(web + __float_as_int(q1.z) + eoff);
            const float4 ee = *(const float4*)(web + __float_as_int(q2.x) + eoff);
            const float4 ef = *(const float4*)(web + __float_as_int(q2.z) + eoff);
            const float4 eg = *(const float4*)(web + __float_as_int(q3.x) + eoff);
            const float4 eh = *(const float4*)(web + __float_as_int(q3.z) + eoff);
            acc0.x += q0.y * ea.x; acc0.y += q0.y * ea.y; acc0.z += q0.y * ea.z; acc0.w += q0.y * ea.w;
            acc1.x += q0.w * eb.x; acc1.y += q0.w * eb.y; acc1.z += q0.w * eb.z; acc1.w += q0.w * eb.w;
            acc0.x += q1.y * ec.x; acc0.y += q1.y * ec.y; acc0.z += q1.y * ec.z; acc0.w += q1.y * ec.w;
            acc1.x += q1.w * ed.x; acc1.y += q1.w * ed.y; acc1.z += q1.w * ed.z; acc1.w += q1.w * ed.w;
            acc0.x += q2.y * ee.x; acc0.y += q2.y * ee.y; acc0.z += q2.y * ee.z; acc0.w += q2.y * ee.w;
            acc1.x += q2.w * ef.x; acc1.y += q2.w * ef.y; acc1.z += q2.w * ef.z; acc1.w += q2.w * ef.w;
            acc0.x += q3.y * eg.x; acc0.y += q3.y * eg.y; acc0.z += q3.y * eg.z; acc0.w += q3.y * eg.w;
            acc1.x += q3.w * eh.x; acc1.y += q3.w * eh.y; acc1.z += q3.w * eh.z; acc1.w += q3.w * eh.w;
        }
    }

    if (active) {
        acc0.x += acc1.x; acc0.y += acc1.y; acc0.z += acc1.z; acc0.w += acc1.w;
        ((float4*)(partial + warp * EMB))[lane] = acc0;
    }
    __syncthreads();

    // deterministic cross-warp reduction
    if (tid < EMB) {
        float d = 0.f;
        #pragma unroll
        for (int w = 0; w < 16; w++) d += partial[w * EMB + tid];
        doc[tid] = d;
    }
    __syncthreads();

    // ---- phase 3: tiny MLP 100 -> 5 -> 100 ----
    if (tid < BOT) {
        float h = __ldg(&fc1b[tid]);
        #pragma unroll
        for (int e = 0; e < EMB; e++) h += doc[e] * __ldg(&fc1w[tid * EMB + e]);
        hv[tid] = h;
    }
    __syncthreads();
    if (tid < EMB) {
        float o = __ldg(&fc2b[tid]);
        #pragma unroll
        for (int j = 0; j < BOT; j++) o += hv[j] * __ldg(&fc2w[tid * BOT + j]);
        out[(long long)blockIdx.x * EMB + tid] = o;
    }
}

extern "C" void kernel_launch(void* const* d_in, const int* in_sizes, int n_in,
                              void* d_out, int out_size)
{
    const int*   x    = (const int*)  d_in[0];   // [B,S] int32 token ids
    const float* we   = (const float*)d_in[1];   // [V,EMB]
    const float* idf  = (const float*)d_in[2];   // [V]
    const float* fc1w = (const float*)d_in[3];   // [BOT,EMB]
    const float* fc1b = (const float*)d_in[4];   // [BOT]
    const float* fc2w = (const float*)d_in[5];   // [EMB,BOT]
    const float* fc2b = (const float*)d_in[6];   // [EMB]
    float* out = (float*)d_out;                  // [B,EMB]

    const int V = in_sizes[2];
    const int B = out_size / EMB;
    const int S = in_sizes[0] / B;

    const int histPad = ((((V + 1) >> 1) + 3) & ~3);
    size_t smem_bytes = (size_t)histPad * 4
                      + (size_t)(16 * 256 + 16 * EMB + 16 + EMB + 8) * 4;

    cudaFuncSetAttribute(doc_model_kernel,
                         cudaFuncAttributeMaxDynamicSharedMemorySize,
                         (int)smem_bytes);

    doc_model_kernel<<<B, NT, smem_bytes>>>(x, we, idf, fc1w, fc1b, fc2w, fc2b,
                                            out, S, V);
}

// round 8
// speedup vs baseline: 1.3779x; 1.0021x over previous
#include <cuda_runtime.h>

#define EMB 100
#define BOT 5
#define NT  512                      // 16 warps -> 128-reg budget per thread
#define FULLMASK 0xffffffffu

// One CTA per document row, 512 threads.
// doc = invZ * [ sum_s idf_s*emb_s  +  sum_{dups} (count_s-1)*idf_s*emb_s ]
// The first gather needs NO histogram counts -> overlaps the atomics phase.
// Smem layout (dynamic, 16B-aligned sections):
//   uint32 hist[histPad]    packed 16-bit token counts
//   float  stage[16*256]    per-warp (offset,idf) pairs; reused as dup queue
//   float  partial[16*EMB]  per-warp doc partials (deterministic reduction)
//   float  zp[16], doc[EMB], hv[8]
__global__ void __launch_bounds__(NT, 1)
doc_model_kernel(const int* __restrict__ x,
                 const float* __restrict__ we,
                 const float* __restrict__ idf,
                 const float* __restrict__ fc1w,
                 const float* __restrict__ fc1b,
                 const float* __restrict__ fc2w,
                 const float* __restrict__ fc2b,
                 float* __restrict__ out,
                 int S, int V)
{
    extern __shared__ unsigned int smem[];
    const int histPad = ((((V + 1) >> 1) + 3) & ~3);
    unsigned int* hist = smem;                    // histPad words
    float* stage   = (float*)(hist + histPad);    // 16 warps * 256 floats
    float* partial = stage + 16 * 256;            // 16*EMB
    float* zp      = partial + 16 * EMB;          // 16
    float* doc     = zp + 16;                     // EMB
    float* hv      = doc + EMB;                   // 8

    const int tid  = threadIdx.x;
    const int warp = tid >> 5;
    const int lane = tid & 31;

    // ---- token load first (one LDG.128): warp w owns tokens [128w, 128w+128),
    // lane l holds tokens 128w + 4l + {0..3}. Latency hides behind zeroing.
    const int* xr = x + (long long)blockIdx.x * S;
    const int4 t4 = *(const int4*)(xr + (warp << 7) + (lane << 2));

    // ---- zero histogram (vectorized) ----
    uint4* h4 = (uint4*)hist;
    const uint4 z4 = make_uint4(0u, 0u, 0u, 0u);
    for (int i = tid; i < (histPad >> 2); i += NT) h4[i] = z4;

    // idf gathers: independent of the histogram, issue before the barrier
    const float i0 = __ldg(&idf[t4.x]);
    const float i1 = __ldg(&idf[t4.y]);
    const float i2 = __ldg(&idf[t4.z]);
    const float i3 = __ldg(&idf[t4.w]);
    __syncthreads();                               // hist zeroed

    // ---- histogram atomics: fire-and-forget, nothing waits on them here ----
    atomicAdd(&hist[t4.x >> 1], 1u << ((t4.x & 1) << 4));
    atomicAdd(&hist[t4.y >> 1], 1u << ((t4.y & 1) << 4));
    atomicAdd(&hist[t4.z >> 1], 1u << ((t4.z & 1) << 4));
    atomicAdd(&hist[t4.w >> 1], 1u << ((t4.w & 1) << 4));

    // ---- stage (byte-offset, idf) pairs for the count-free gather ----
    float4* stW = (float4*)(stage + (warp << 8));
    stW[(lane << 1)]     = make_float4(__int_as_float(t4.x * (EMB * 4)), i0,
                                       __int_as_float(t4.y * (EMB * 4)), i1);
    stW[(lane << 1) + 1] = make_float4(__int_as_float(t4.z * (EMB * 4)), i2,
                                       __int_as_float(t4.w * (EMB * 4)), i3);

    // Z partial (idf only -- no counts needed)
    float z = (i0 + i1) + (i2 + i3);
    #pragma unroll
    for (int o = 16; o; o >>= 1) z += __shfl_xor_sync(FULLMASK, z, o);
    if (lane == 0) zp[warp] = z;
    __syncwarp();

    // ---- MAIN GATHER (overlaps the histogram atomics completing) ----
    const bool active = lane < (EMB / 4);   // 25 lanes carry the embedding row
    const int  eoff   = lane << 4;
    const char* web = (const char*)we;
    float4 acc0 = make_float4(0.f, 0.f, 0.f, 0.f);
    float4 acc1 = make_float4(0.f, 0.f, 0.f, 0.f);

    #pragma unroll 2
    for (int kk = 0; kk < 64; kk += 4) {
        const float4 q0 = stW[kk];
        const float4 q1 = stW[kk + 1];
        const float4 q2 = stW[kk + 2];
        const float4 q3 = stW[kk + 3];
        if (active) {
            const float4 ea = *(const float4*)(web + __float_as_int(q0.x) + eoff);
            const float4 eb = *(const float4*)(web + __float_as_int(q0.z) + eoff);
            const float4 ec = *(const float4*)(web + __float_as_int(q1.x) + eoff);
            const float4 ed = *(const float4*)(web + __float_as_int(q1.z) + eoff);
            const float4 ee = *(const float4*)(web + __float_as_int(q2.x) + eoff);
            const float4 ef = *(const float4*)(web + __float_as_int(q2.z) + eoff);
            const float4 eg = *(const float4*)(web + __float_as_int(q3.x) + eoff);
            const float4 eh = *(const float4*)(web + __float_as_int(q3.z) + eoff);
            acc0.x += q0.y * ea.x; acc0.y += q0.y * ea.y; acc0.z += q0.y * ea.z; acc0.w += q0.y * ea.w;
            acc1.x += q0.w * eb.x; acc1.y += q0.w * eb.y; acc1.z += q0.w * eb.z; acc1.w += q0.w * eb.w;
            acc0.x += q1.y * ec.x; acc0.y += q1.y * ec.y; acc0.z += q1.y * ec.z; acc0.w += q1.y * ec.w;
            acc1.x += q1.w * ed.x; acc1.y += q1.w * ed.y; acc1.z += q1.w * ed.z; acc1.w += q1.w * ed.w;
            acc0.x += q2.y * ee.x; acc0.y += q2.y * ee.y; acc0.z += q2.y * ee.z; acc0.w += q2.y * ee.w;
            acc1.x += q2.w * ef.x; acc1.y += q2.w * ef.y; acc1.z += q2.w * ef.z; acc1.w += q2.w * ef.w;
            acc0.x += q3.y * eg.x; acc0.y += q3.y * eg.y; acc0.z += q3.y * eg.z; acc0.w += q3.y * eg.w;
            acc1.x += q3.w * eh.x; acc1.y += q3.w * eh.y; acc1.z += q3.w * eh.z; acc1.w += q3.w * eh.w;
        }
    }

    __syncthreads();   // all histogram atomics + zp now visible

    float zz = 0.f;
    #pragma unroll
    for (int i = 0; i < 16; i++) zz += zp[i];
    const float invZ = 1.0f / zz;

    // ---- duplicate correction: queue (offset, (count-1)*idf) for count>=2.
    // Expected ~83 duplicated occurrences per ROW (~5 per warp).
    const unsigned n0 = (hist[t4.x >> 1] >> ((t4.x & 1) << 4)) & 0xFFFFu;
    const unsigned n1 = (hist[t4.y >> 1] >> ((t4.y & 1) << 4)) & 0xFFFFu;
    const unsigned n2 = (hist[t4.z >> 1] >> ((t4.z & 1) << 4)) & 0xFFFFu;
    const unsigned n3 = (hist[t4.w >> 1] >> ((t4.w & 1) << 4)) & 0xFFFFu;
    __syncwarp();                                   // strip reuse is now safe

    float2* q = (float2*)(stage + (warp << 8));     // capacity 128 entries
    int qlen = 0;
    {
        const unsigned lt = (1u << lane) - 1u;
        unsigned m;
        m = __ballot_sync(FULLMASK, n0 > 1);
        if (n0 > 1) q[qlen + __popc(m & lt)] =
            make_float2(__int_as_float(t4.x * (EMB * 4)), (float)(n0 - 1) * i0);
        qlen += __popc(m);
        m = __ballot_sync(FULLMASK, n1 > 1);
        if (n1 > 1) q[qlen + __popc(m & lt)] =
            make_float2(__int_as_float(t4.y * (EMB * 4)), (float)(n1 - 1) * i1);
        qlen += __popc(m);
        m = __ballot_sync(FULLMASK, n2 > 1);
        if (n2 > 1) q[qlen + __popc(m & lt)] =
            make_float2(__int_as_float(t4.z * (EMB * 4)), (float)(n2 - 1) * i2);
        qlen += __popc(m);
        m = __ballot_sync(FULLMASK, n3 > 1);
        if (n3 > 1) q[qlen + __popc(m & lt)] =
            make_float2(__int_as_float(t4.w * (EMB * 4)), (float)(n3 - 1) * i3);
        qlen += __popc(m);
    }
    __syncwarp();

    for (int j = 0; j < qlen; j++) {
        const float2 e = q[j];
        if (active) {
            const float4 ev = *(const float4*)(web + __float_as_int(e.x) + eoff);
            acc0.x += e.y * ev.x; acc0.y += e.y * ev.y;
            acc0.z += e.y * ev.z; acc0.w += e.y * ev.w;
        }
    }

    if (active) {
        acc0.x += acc1.x; acc0.y += acc1.y; acc0.z += acc1.z; acc0.w += acc1.w;
        ((float4*)(partial + warp * EMB))[lane] = acc0;
    }
    __syncthreads();

    // deterministic cross-warp reduction, scaled by invZ
    if (tid < EMB) {
        float d = 0.f;
        #pragma unroll
        for (int w = 0; w < 16; w++) d += partial[w * EMB + tid];
        doc[tid] = d * invZ;
    }
    __syncthreads();

    // ---- tiny MLP 100 -> 5 -> 100 ----
    if (tid < BOT) {
        float h = __ldg(&fc1b[tid]);
        #pragma unroll
        for (int e = 0; e < EMB; e++) h += doc[e] * __ldg(&fc1w[tid * EMB + e]);
        hv[tid] = h;
    }
    __syncthreads();
    if (tid < EMB) {
        float o = __ldg(&fc2b[tid]);
        #pragma unroll
        for (int j = 0; j < BOT; j++) o += hv[j] * __ldg(&fc2w[tid * BOT + j]);
        out[(long long)blockIdx.x * EMB + tid] = o;
    }
}

extern "C" void kernel_launch(void* const* d_in, const int* in_sizes, int n_in,
                              void* d_out, int out_size)
{
    const int*   x    = (const int*)  d_in[0];   // [B,S] int32 token ids
    const float* we   = (const float*)d_in[1];   // [V,EMB]
    const float* idf  = (const float*)d_in[2];   // [V]
    const float* fc1w = (const float*)d_in[3];   // [BOT,EMB]
    const float* fc1b = (const float*)d_in[4];   // [BOT]
    const float* fc2w = (const float*)d_in[5];   // [EMB,BOT]
    const float* fc2b = (const float*)d_in[6];   // [EMB]
    float* out = (float*)d_out;                  // [B,EMB]

    const int V = in_sizes[2];
    const int B = out_size / EMB;
    const int S = in_sizes[0] / B;

    const int histPad = ((((V + 1) >> 1) + 3) & ~3);
    size_t smem_bytes = (size_t)histPad * 4
                      + (size_t)(16 * 256 + 16 * EMB + 16 + EMB + 8) * 4;

    cudaFuncSetAttribute(doc_model_kernel,
                         cudaFuncAttributeMaxDynamicSharedMemorySize,
                         (int)smem_bytes);

    doc_model_kernel<<<B, NT, smem_bytes>>>(x, we, idf, fc1w, fc1b, fc2w, fc2b,
                                            out, S, V);
}